// round 2
// baseline (speedup 1.0000x reference)
#include <cuda_runtime.h>
#include <cuda_bf16.h>
#include <cstddef>

#define NN 200000
#define EMBD 128

typedef unsigned long long u64;

// ---------------- scratch (device globals; no allocation) ----------------
__device__ float g_h [(size_t)NN * EMBD];   // current node rep
__device__ float g_P [(size_t)NN * EMBD];   // dis[row]*relu(xl) messages
__device__ float g_A [(size_t)NN * EMBD];   // agg buffer 1
__device__ float g_B [(size_t)NN * EMBD];   // agg buffer 2
__device__ float g_H1[(size_t)NN * 256];    // encoder hidden
__device__ float g_deg0[NN], g_deg1[NN];
__device__ float g_dis0[NN], g_dis1[NN];    // deg^-0.5
__device__ float g_dinv0[NN], g_dinv1[NN];  // 1/deg

__device__ __forceinline__ float leaky_f(float v) { return v >= 0.f ? v : 0.1f * v; }
__device__ __forceinline__ float relu_f(float v)  { return v > 0.f ? v : 0.f; }

__device__ __forceinline__ u64 pack2(float lo, float hi) {
    u64 d;
    asm("mov.b64 %0, {%1, %2};" : "=l"(d) : "f"(lo), "f"(hi));
    return d;
}
__device__ __forceinline__ void unpack2(u64 d, float& lo, float& hi) {
    asm("mov.b64 {%0, %1}, %2;" : "=f"(lo), "=f"(hi) : "l"(d));
}
__device__ __forceinline__ void ffma2(u64& d, u64 a, u64 b) {
    asm("fma.rn.f32x2 %0, %1, %2, %0;" : "+l"(d) : "l"(a), "l"(b));
}

// ---------------- degree kernels ----------------
__global__ void k_initdeg() {
    int i = blockIdx.x * 256 + threadIdx.x;
    if (i < NN) { g_deg0[i] = 1.f; g_deg1[i] = 1.f; }
}

__global__ void k_count(const int* __restrict__ edges, float* __restrict__ deg, int E) {
    int i = blockIdx.x * 256 + threadIdx.x;
    if (i < E) atomicAdd(&deg[edges[i]], 1.f);
}

__global__ void k_finishdeg() {
    int i = blockIdx.x * 256 + threadIdx.x;
    if (i < NN) {
        float d0 = g_deg0[i], d1 = g_deg1[i];
        g_dis0[i] = rsqrtf(d0); g_dinv0[i] = 1.0f / d0;
        g_dis1[i] = rsqrtf(d1); g_dinv1[i] = 1.0f / d1;
    }
}

// ---------------- encoder layer 1: H1 = leaky(x @ W1 + b1), K=32, Nout=256 ----------------
__global__ void k_enc1(const float* __restrict__ x, const float* __restrict__ W1,
                       const float* __restrict__ b1) {
    __shared__ float sW[32 * 256];
    int t = threadIdx.x;
    {
        float4* sv = (float4*)sW;
        const float4* wv = (const float4*)W1;
        #pragma unroll
        for (int i = 0; i < 8; i++) sv[t + 256 * i] = wv[t + 256 * i];
    }
    __syncthreads();
    int wid = t >> 5, lane = t & 31;
    int node = blockIdx.x * 8 + wid;
    float xv = x[(size_t)node * 32 + lane];
    float acc[8];
    #pragma unroll
    for (int i = 0; i < 8; i++) acc[i] = b1[lane + 32 * i];
    #pragma unroll
    for (int k = 0; k < 32; k++) {
        float xk = __shfl_sync(0xffffffffu, xv, k);
        #pragma unroll
        for (int i = 0; i < 8; i++) acc[i] += xk * sW[k * 256 + lane + 32 * i];
    }
    float* dst = g_H1 + (size_t)node * 256;
    #pragma unroll
    for (int i = 0; i < 8; i++) dst[lane + 32 * i] = leaky_f(acc[i]);
}

// ---------------- f32x2 GEMM: C[64 x 128] tile of A[M,K] @ W[K,128] ----------------
// Thread t covers rows r0+ty+8i (i=0..7), cols tx+32j (j=0..3).
// mode 0: h = leaky(acc+bias) -> AGG; also out[r*512+c] for r < NI     (encoder layer 2)
// mode 1: P = dis[r]*relu(acc+bias); AGG = relu(acc+bias+root)*dinv[r]  (GCN linear)
__global__ void __launch_bounds__(256, 2)
k_gemm(const float* __restrict__ A, const float* __restrict__ W,
       const float* __restrict__ bias, const float* __restrict__ root,
       const float* __restrict__ dinv, const float* __restrict__ dis,
       float* __restrict__ P, float* __restrict__ AGG, float* __restrict__ out,
       int K, int mode, int NI) {
    __shared__ float sA[64 * 64];
    __shared__ float sW[64 * 128];
    int t = threadIdx.x;
    int tx = t & 31, ty = t >> 5;
    int r0 = blockIdx.x * 64;

    u64 acc[8][4];   // packed pair-sums over (even k, odd k)
    u64 zz = pack2(0.f, 0.f);
    #pragma unroll
    for (int i = 0; i < 8; i++)
        #pragma unroll
        for (int j = 0; j < 4; j++) acc[i][j] = zz;

    for (int kc = 0; kc < K; kc += 64) {
        // load A tile: 64 rows x 64 cols
        #pragma unroll
        for (int i = 0; i < 4; i++) {
            int idx = t + 256 * i;
            int r = idx >> 4, c = idx & 15;
            ((float4*)sA)[idx] = *(const float4*)(A + (size_t)(r0 + r) * K + kc + c * 4);
        }
        // load W tile: 64 rows x 128 cols
        #pragma unroll
        for (int i = 0; i < 8; i++) {
            int idx = t + 256 * i;
            int r = idx >> 5, c = idx & 31;
            ((float4*)sW)[idx] = *(const float4*)(W + (size_t)(kc + r) * 128 + c * 4);
        }
        __syncthreads();
        #pragma unroll
        for (int kk = 0; kk < 64; kk += 4) {
            u64 a01[8], a23[8];
            #pragma unroll
            for (int i = 0; i < 8; i++) {
                float4 a4 = *(const float4*)&sA[(ty + 8 * i) * 64 + kk];  // broadcast
                a01[i] = pack2(a4.x, a4.y);
                a23[i] = pack2(a4.z, a4.w);
            }
            #pragma unroll
            for (int j = 0; j < 4; j++) {
                int c = tx + 32 * j;
                u64 w01 = pack2(sW[kk * 128 + c],       sW[(kk + 1) * 128 + c]);
                u64 w23 = pack2(sW[(kk + 2) * 128 + c], sW[(kk + 3) * 128 + c]);
                #pragma unroll
                for (int i = 0; i < 8; i++) {
                    ffma2(acc[i][j], a01[i], w01);
                    ffma2(acc[i][j], a23[i], w23);
                }
            }
        }
        __syncthreads();
    }

    // horizontal reduce pairs
    float res[8][4];
    #pragma unroll
    for (int i = 0; i < 8; i++)
        #pragma unroll
        for (int j = 0; j < 4; j++) {
            float lo, hi; unpack2(acc[i][j], lo, hi);
            res[i][j] = lo + hi;
        }

    float bv[4], rv[4];
    #pragma unroll
    for (int j = 0; j < 4; j++) bv[j] = bias[tx + 32 * j];
    if (mode == 1) {
        #pragma unroll
        for (int j = 0; j < 4; j++) rv[j] = root[tx + 32 * j];
    }

    if (mode == 0) {
        #pragma unroll
        for (int i = 0; i < 8; i++) {
            int r = r0 + ty + 8 * i;
            #pragma unroll
            for (int j = 0; j < 4; j++) {
                float v = leaky_f(res[i][j] + bv[j]);
                AGG[(size_t)r * 128 + tx + 32 * j] = v;
                if (r < NI) out[(size_t)r * 512 + tx + 32 * j] = v;
            }
        }
    } else {
        #pragma unroll
        for (int i = 0; i < 8; i++) {
            int r = r0 + ty + 8 * i;
            float di = dinv[r];
            float ds = dis[r];
            #pragma unroll
            for (int j = 0; j < 4; j++) {
                float v = res[i][j] + bv[j];
                P[(size_t)r * 128 + tx + 32 * j] = ds * relu_f(v);
                AGG[(size_t)r * 128 + tx + 32 * j] = relu_f(v + rv[j]) * di;
            }
        }
    }
}

// ---------------- scatter: AGG[col] += dis[col] * P[row], warp per edge, v4 RED ----------------
__global__ void k_scatter(const int* __restrict__ edges, const float* __restrict__ dis,
                          const float* __restrict__ P, float* __restrict__ AGG, int E) {
    int w = (blockIdx.x * blockDim.x + threadIdx.x) >> 5;
    if (w >= E) return;
    int lane = threadIdx.x & 31;
    int row = __ldg(&edges[w]);
    int col = __ldg(&edges[E + w]);
    float nrm = __ldg(&dis[col]);          // dis[row] pre-folded into P
    const float4* src = (const float4*)(P + (size_t)row * 128);
    float4* dst = (float4*)(AGG + (size_t)col * 128);
    float4 v = __ldg(&src[lane]);
    asm volatile("red.global.add.v4.f32 [%0], {%1, %2, %3, %4};"
                 :: "l"(dst + lane), "f"(nrm * v.x), "f"(nrm * v.y),
                    "f"(nrm * v.z), "f"(nrm * v.w)
                 : "memory");
}

// ---------------- layernorm + leaky + residual, warp per node ----------------
__global__ void k_ln(const float* __restrict__ Bin, const float* __restrict__ gamma,
                     const float* __restrict__ beta, float* __restrict__ h,
                     float* __restrict__ out, int l, int NI) {
    int t = threadIdx.x;
    int lane = t & 31;
    int node = blockIdx.x * 8 + (t >> 5);
    float4 v = ((const float4*)(Bin + (size_t)node * 128))[lane];
    float s = v.x + v.y + v.z + v.w;
    #pragma unroll
    for (int o = 16; o > 0; o >>= 1) s += __shfl_xor_sync(0xffffffffu, s, o);
    float mu = s * (1.0f / 128.0f);
    float dx = v.x - mu, dy = v.y - mu, dz = v.z - mu, dw = v.w - mu;
    float q = dx * dx + dy * dy + dz * dz + dw * dw;
    #pragma unroll
    for (int o = 16; o > 0; o >>= 1) q += __shfl_xor_sync(0xffffffffu, q, o);
    float rs = rsqrtf(q * (1.0f / 128.0f) + 1e-5f);
    float4 gg = ((const float4*)gamma)[lane];
    float4 bb = ((const float4*)beta)[lane];
    float4 hp = ((const float4*)(h + (size_t)node * 128))[lane];
    float4 o4;
    o4.x = leaky_f(dx * rs * gg.x + bb.x) + hp.x;
    o4.y = leaky_f(dy * rs * gg.y + bb.y) + hp.y;
    o4.z = leaky_f(dz * rs * gg.z + bb.z) + hp.z;
    o4.w = leaky_f(dw * rs * gg.w + bb.w) + hp.w;
    ((float4*)(h + (size_t)node * 128))[lane] = o4;
    if (node < NI) ((float4*)(out + (size_t)node * 512 + (l + 1) * 128))[lane] = o4;
}

// ---------------- host ----------------
extern "C" void kernel_launch(void* const* d_in, const int* in_sizes, int n_in,
                              void* d_out, int out_size) {
    const float* x    = (const float*)d_in[0];
    const float* ew1  = (const float*)d_in[1];
    const float* eb1  = (const float*)d_in[2];
    const float* ew2  = (const float*)d_in[3];
    const float* eb2  = (const float*)d_in[4];
    const float* cw   = (const float*)d_in[5];
    const float* cb   = (const float*)d_in[6];
    const float* cr   = (const float*)d_in[7];
    const float* rw   = (const float*)d_in[8];
    const float* rb   = (const float*)d_in[9];
    const float* rr   = (const float*)d_in[10];
    const float* lg   = (const float*)d_in[11];
    const float* lb   = (const float*)d_in[12];
    const int* e_nn   = (const int*)d_in[13];
    const int* e_net  = (const int*)d_in[14];
    float* out = (float*)d_out;

    int E  = in_sizes[13] / 2;
    int NI = out_size / 512;

    float *p_h, *p_P, *p_A, *p_B, *p_H1;
    float *p_deg0, *p_deg1, *p_dis0, *p_dis1, *p_dinv0, *p_dinv1;
    cudaGetSymbolAddress((void**)&p_h, g_h);
    cudaGetSymbolAddress((void**)&p_P, g_P);
    cudaGetSymbolAddress((void**)&p_A, g_A);
    cudaGetSymbolAddress((void**)&p_B, g_B);
    cudaGetSymbolAddress((void**)&p_H1, g_H1);
    cudaGetSymbolAddress((void**)&p_deg0, g_deg0);
    cudaGetSymbolAddress((void**)&p_deg1, g_deg1);
    cudaGetSymbolAddress((void**)&p_dis0, g_dis0);
    cudaGetSymbolAddress((void**)&p_dis1, g_dis1);
    cudaGetSymbolAddress((void**)&p_dinv0, g_dinv0);
    cudaGetSymbolAddress((void**)&p_dinv1, g_dinv1);

    const int nblkN = (NN + 255) / 256;
    const int nblkE = (E + 255) / 256;

    k_initdeg<<<nblkN, 256>>>();
    k_count<<<nblkE, 256>>>(e_nn, p_deg0, E);
    k_count<<<nblkE, 256>>>(e_net, p_deg1, E);
    k_finishdeg<<<nblkN, 256>>>();

    k_enc1<<<NN / 8, 256>>>(x, ew1, eb1);
    k_gemm<<<NN / 64, 256>>>(p_H1, ew2, eb2, nullptr, nullptr, nullptr, nullptr,
                             p_h, out, 256, 0, NI);

    const int scblk = (E * 32 + 255) / 256;
    for (int l = 0; l < 3; l++) {
        k_gemm<<<NN / 64, 256>>>(p_h, cw + l * 16384, cb + l * 128, cr + l * 128,
                                 p_dinv0, p_dis0, p_P, p_A, nullptr, 128, 1, NI);
        k_scatter<<<scblk, 256>>>(e_nn, p_dis0, p_P, p_A, E);
        k_gemm<<<NN / 64, 256>>>(p_A, rw + l * 16384, rb + l * 128, rr + l * 128,
                                 p_dinv1, p_dis1, p_P, p_B, nullptr, 128, 1, NI);
        k_scatter<<<scblk, 256>>>(e_net, p_dis1, p_P, p_B, E);
        k_ln<<<NN / 8, 256>>>(p_B, lg + l * 128, lb + l * 128, p_h, out, l, NI);
    }
}

// round 4
// speedup vs baseline: 1.7498x; 1.7498x over previous
#include <cuda_runtime.h>
#include <cuda_fp16.h>
#include <cstdint>
#include <cstddef>

#define NN 200000
#define EMBD 128
#define LDA 136   // padded row stride in halves

// ---------------- scratch (device globals; no allocation) ----------------
__device__ float g_h [(size_t)NN * EMBD];
__device__ float g_P [(size_t)NN * EMBD];
__device__ float g_A [(size_t)NN * EMBD];
__device__ float g_B [(size_t)NN * EMBD];
__device__ float g_H1[(size_t)NN * 256];
__device__ float g_deg0[NN], g_deg1[NN];
__device__ float g_dis0[NN], g_dis1[NN];
__device__ float g_dinv0[NN], g_dinv1[NN];

__device__ __forceinline__ float leaky_f(float v) { return v >= 0.f ? v : 0.1f * v; }
__device__ __forceinline__ float relu_f(float v)  { return v > 0.f ? v : 0.f; }

__device__ __forceinline__ uint32_t smem_u32(const void* p) {
    uint32_t a;
    asm("{ .reg .u64 t; cvta.to.shared.u64 t, %1; cvt.u32.u64 %0, t; }" : "=r"(a) : "l"(p));
    return a;
}
__device__ __forceinline__ void ldsm_x4(uint32_t* r, uint32_t a) {
    asm volatile("ldmatrix.sync.aligned.m8n8.x4.shared.b16 {%0,%1,%2,%3}, [%4];"
                 : "=r"(r[0]), "=r"(r[1]), "=r"(r[2]), "=r"(r[3]) : "r"(a));
}
__device__ __forceinline__ void ldsm_x4t(uint32_t* r, uint32_t a) {
    asm volatile("ldmatrix.sync.aligned.m8n8.x4.trans.shared.b16 {%0,%1,%2,%3}, [%4];"
                 : "=r"(r[0]), "=r"(r[1]), "=r"(r[2]), "=r"(r[3]) : "r"(a));
}
__device__ __forceinline__ void mma_fp16(float* d, const uint32_t* a, const uint32_t* b) {
    asm volatile("mma.sync.aligned.m16n8k16.row.col.f32.f16.f16.f32 "
                 "{%0,%1,%2,%3}, {%4,%5,%6,%7}, {%8,%9}, {%0,%1,%2,%3};"
                 : "+f"(d[0]), "+f"(d[1]), "+f"(d[2]), "+f"(d[3])
                 : "r"(a[0]), "r"(a[1]), "r"(a[2]), "r"(a[3]), "r"(b[0]), "r"(b[1]));
}

// ---------------- degree kernels ----------------
__global__ void k_initdeg() {
    int i = blockIdx.x * 256 + threadIdx.x;
    if (i < NN) { g_deg0[i] = 1.f; g_deg1[i] = 1.f; }
}
__global__ void k_count(const int* __restrict__ edges, float* __restrict__ deg, int E) {
    int i = blockIdx.x * 256 + threadIdx.x;
    if (i < E) atomicAdd(&deg[edges[i]], 1.f);
}
__global__ void k_finishdeg() {
    int i = blockIdx.x * 256 + threadIdx.x;
    if (i < NN) {
        float d0 = g_deg0[i], d1 = g_deg1[i];
        g_dis0[i] = rsqrtf(d0); g_dinv0[i] = 1.0f / d0;
        g_dis1[i] = rsqrtf(d1); g_dinv1[i] = 1.0f / d1;
    }
}

// ---------------- encoder layer 1 ----------------
__global__ void k_enc1(const float* __restrict__ x, const float* __restrict__ W1,
                       const float* __restrict__ b1) {
    __shared__ float sW[32 * 256];
    int t = threadIdx.x;
    {
        float4* sv = (float4*)sW;
        const float4* wv = (const float4*)W1;
        #pragma unroll
        for (int i = 0; i < 8; i++) sv[t + 256 * i] = wv[t + 256 * i];
    }
    __syncthreads();
    int wid = t >> 5, lane = t & 31;
    int node = blockIdx.x * 8 + wid;
    float xv = x[(size_t)node * 32 + lane];
    float acc[8];
    #pragma unroll
    for (int i = 0; i < 8; i++) acc[i] = b1[lane + 32 * i];
    #pragma unroll
    for (int k = 0; k < 32; k++) {
        float xk = __shfl_sync(0xffffffffu, xv, k);
        #pragma unroll
        for (int i = 0; i < 8; i++) acc[i] += xk * sW[k * 256 + lane + 32 * i];
    }
    float* dst = g_H1 + (size_t)node * 256;
    #pragma unroll
    for (int i = 0; i < 8; i++) dst[lane + 32 * i] = leaky_f(acc[i]);
}

// ---------------- HMMA GEMM: C[128x128] = A[M,K] @ W[K,128], fp16 3-pass split ----
// mode 0: h = leaky(acc+bias) -> AGG; also out[r*512+c] for r < NI
// mode 1: P = dis[r]*relu(acc+bias); AGG = relu(acc+bias+root)*dinv[r]
#define SM_HALVES (128 * LDA)
#define SM_BYTES  (4 * SM_HALVES * 2)

__global__ void __launch_bounds__(256)
k_mma(const float* __restrict__ A, const float* __restrict__ W,
      const float* __restrict__ bias, const float* __restrict__ root,
      const float* __restrict__ dinv, const float* __restrict__ dis,
      float* __restrict__ P, float* __restrict__ AGG, float* __restrict__ out,
      int K, int mode, int NI) {
    extern __shared__ __half smem[];
    __half* sAh = smem;
    __half* sAl = smem + SM_HALVES;
    __half* sBh = smem + 2 * SM_HALVES;
    __half* sBl = smem + 3 * SM_HALVES;

    int tid = threadIdx.x, lane = tid & 31, w = tid >> 5;
    int wm = w & 3, wn = w >> 2;
    int r0 = blockIdx.x * 128;

    float acc[2][8][4];
    #pragma unroll
    for (int i = 0; i < 2; i++)
        #pragma unroll
        for (int n = 0; n < 8; n++)
            #pragma unroll
            for (int q = 0; q < 4; q++) acc[i][n][q] = 0.f;

    uint32_t sb = smem_u32(smem);
    // ldmatrix lane addressing: row = lane&15, col-half = lane>>4
    uint32_t aAh = sb + 2 * ((wm * 32 + (lane & 15)) * LDA + (lane >> 4) * 8);
    uint32_t aAl = aAh + 2 * SM_HALVES * 2;   // offset of sAl in bytes is SM_HALVES*2; aAh already in bytes
    aAl = aAh + SM_HALVES * 2;
    uint32_t aBh = sb + 2 * (2 * SM_HALVES) + 2 * ((lane & 15) * LDA + wn * 64 + (lane >> 4) * 8);
    uint32_t aBl = aBh + SM_HALVES * 2;

    for (int kc = 0; kc < K; kc += 128) {
        if (kc) __syncthreads();
        // ---- stage A (128 rows x 128 k) as fp16 hi/lo ----
        #pragma unroll
        for (int i = 0; i < 16; i++) {
            int idx = tid + 256 * i;
            int r = idx >> 5, kg = (idx & 31) * 4;
            int rr = r0 + r; if (rr >= NN) rr = NN - 1;
            float4 a = *(const float4*)(A + (size_t)rr * K + kc + kg);
            __half2 h01 = __floats2half2_rn(a.x, a.y);
            __half2 h23 = __floats2half2_rn(a.z, a.w);
            float2 f01 = __half22float2(h01);
            float2 f23 = __half22float2(h23);
            __half2 l01 = __floats2half2_rn(a.x - f01.x, a.y - f01.y);
            __half2 l23 = __floats2half2_rn(a.z - f23.x, a.w - f23.y);
            int off = r * LDA + kg;
            uint2 vh; vh.x = *(uint32_t*)&h01; vh.y = *(uint32_t*)&h23;
            uint2 vl; vl.x = *(uint32_t*)&l01; vl.y = *(uint32_t*)&l23;
            *(uint2*)(sAh + off) = vh;
            *(uint2*)(sAl + off) = vl;
        }
        // ---- stage W chunk (128 k-rows x 128 n) as fp16 hi/lo ----
        #pragma unroll
        for (int i = 0; i < 16; i++) {
            int idx = tid + 256 * i;
            int kk = idx >> 5, ng = (idx & 31) * 4;
            float4 a = *(const float4*)(W + (size_t)(kc + kk) * 128 + ng);
            __half2 h01 = __floats2half2_rn(a.x, a.y);
            __half2 h23 = __floats2half2_rn(a.z, a.w);
            float2 f01 = __half22float2(h01);
            float2 f23 = __half22float2(h23);
            __half2 l01 = __floats2half2_rn(a.x - f01.x, a.y - f01.y);
            __half2 l23 = __floats2half2_rn(a.z - f23.x, a.w - f23.y);
            int off = kk * LDA + ng;
            uint2 vh; vh.x = *(uint32_t*)&h01; vh.y = *(uint32_t*)&h23;
            uint2 vl; vl.x = *(uint32_t*)&l01; vl.y = *(uint32_t*)&l23;
            *(uint2*)(sBh + off) = vh;
            *(uint2*)(sBl + off) = vl;
        }
        __syncthreads();

        // ---- mainloop: 8 k-steps of k16 ----
        #pragma unroll
        for (int ks = 0; ks < 8; ks++) {
            uint32_t ah[2][4], al[2][4];
            #pragma unroll
            for (int i = 0; i < 2; i++) {
                ldsm_x4(ah[i], aAh + i * (16 * LDA * 2) + ks * 32);
                ldsm_x4(al[i], aAl + i * (16 * LDA * 2) + ks * 32);
            }
            uint32_t bh[4][4], bl[4][4];
            #pragma unroll
            for (int j = 0; j < 4; j++) {
                ldsm_x4t(bh[j], aBh + ks * (16 * LDA * 2) + j * 32);
                ldsm_x4t(bl[j], aBl + ks * (16 * LDA * 2) + j * 32);
            }
            #pragma unroll
            for (int i = 0; i < 2; i++)
                #pragma unroll
                for (int j = 0; j < 4; j++) {
                    mma_fp16(acc[i][2 * j],     ah[i], &bh[j][0]);
                    mma_fp16(acc[i][2 * j + 1], ah[i], &bh[j][2]);
                    mma_fp16(acc[i][2 * j],     al[i], &bh[j][0]);
                    mma_fp16(acc[i][2 * j + 1], al[i], &bh[j][2]);
                    mma_fp16(acc[i][2 * j],     ah[i], &bl[j][0]);
                    mma_fp16(acc[i][2 * j + 1], ah[i], &bl[j][2]);
                }
        }
    }

    // ---- epilogue ----
    int rbase = r0 + wm * 32;
    int cb = wn * 64 + (lane & 3) * 2;
    #pragma unroll
    for (int i = 0; i < 2; i++) {
        #pragma unroll
        for (int q2 = 0; q2 < 2; q2++) {
            int r = rbase + i * 16 + (lane >> 2) + q2 * 8;
            if (r >= NN) continue;
            if (mode == 0) {
                #pragma unroll
                for (int n = 0; n < 8; n++) {
                    int c = cb + n * 8;
                    float2 o;
                    o.x = leaky_f(acc[i][n][q2 * 2]     + bias[c]);
                    o.y = leaky_f(acc[i][n][q2 * 2 + 1] + bias[c + 1]);
                    *(float2*)(AGG + (size_t)r * 128 + c) = o;
                    if (r < NI) *(float2*)(out + (size_t)r * 512 + c) = o;
                }
            } else {
                float di = dinv[r], ds = dis[r];
                #pragma unroll
                for (int n = 0; n < 8; n++) {
                    int c = cb + n * 8;
                    float v0 = acc[i][n][q2 * 2]     + bias[c];
                    float v1 = acc[i][n][q2 * 2 + 1] + bias[c + 1];
                    float2 p, s;
                    p.x = ds * relu_f(v0); p.y = ds * relu_f(v1);
                    s.x = relu_f(v0 + root[c]) * di;
                    s.y = relu_f(v1 + root[c + 1]) * di;
                    *(float2*)(P   + (size_t)r * 128 + c) = p;
                    *(float2*)(AGG + (size_t)r * 128 + c) = s;
                }
            }
        }
    }
}

// ---------------- scatter: AGG[col] += dis[col] * P[row], warp per edge ----------------
__global__ void k_scatter(const int* __restrict__ edges, const float* __restrict__ dis,
                          const float* __restrict__ P, float* __restrict__ AGG, int E) {
    int w = (blockIdx.x * blockDim.x + threadIdx.x) >> 5;
    if (w >= E) return;
    int lane = threadIdx.x & 31;
    int row = __ldg(&edges[w]);
    int col = __ldg(&edges[E + w]);
    float nrm = __ldg(&dis[col]);
    const float4* src = (const float4*)(P + (size_t)row * 128);
    float4* dst = (float4*)(AGG + (size_t)col * 128);
    float4 v = __ldg(&src[lane]);
    asm volatile("red.global.add.v4.f32 [%0], {%1, %2, %3, %4};"
                 :: "l"(dst + lane), "f"(nrm * v.x), "f"(nrm * v.y),
                    "f"(nrm * v.z), "f"(nrm * v.w)
                 : "memory");
}

// ---------------- layernorm + leaky + residual ----------------
__global__ void k_ln(const float* __restrict__ Bin, const float* __restrict__ gamma,
                     const float* __restrict__ beta, float* __restrict__ h,
                     float* __restrict__ out, int l, int NI) {
    int t = threadIdx.x;
    int lane = t & 31;
    int node = blockIdx.x * 8 + (t >> 5);
    float4 v = ((const float4*)(Bin + (size_t)node * 128))[lane];
    float s = v.x + v.y + v.z + v.w;
    #pragma unroll
    for (int o = 16; o > 0; o >>= 1) s += __shfl_xor_sync(0xffffffffu, s, o);
    float mu = s * (1.0f / 128.0f);
    float dx = v.x - mu, dy = v.y - mu, dz = v.z - mu, dw = v.w - mu;
    float q = dx * dx + dy * dy + dz * dz + dw * dw;
    #pragma unroll
    for (int o = 16; o > 0; o >>= 1) q += __shfl_xor_sync(0xffffffffu, q, o);
    float rs = rsqrtf(q * (1.0f / 128.0f) + 1e-5f);
    float4 gg = ((const float4*)gamma)[lane];
    float4 bb = ((const float4*)beta)[lane];
    float4 hp = ((const float4*)(h + (size_t)node * 128))[lane];
    float4 o4;
    o4.x = leaky_f(dx * rs * gg.x + bb.x) + hp.x;
    o4.y = leaky_f(dy * rs * gg.y + bb.y) + hp.y;
    o4.z = leaky_f(dz * rs * gg.z + bb.z) + hp.z;
    o4.w = leaky_f(dw * rs * gg.w + bb.w) + hp.w;
    ((float4*)(h + (size_t)node * 128))[lane] = o4;
    if (node < NI) ((float4*)(out + (size_t)node * 512 + (l + 1) * 128))[lane] = o4;
}

// ---------------- host ----------------
extern "C" void kernel_launch(void* const* d_in, const int* in_sizes, int n_in,
                              void* d_out, int out_size) {
    const float* x    = (const float*)d_in[0];
    const float* ew1  = (const float*)d_in[1];
    const float* eb1  = (const float*)d_in[2];
    const float* ew2  = (const float*)d_in[3];
    const float* eb2  = (const float*)d_in[4];
    const float* cw   = (const float*)d_in[5];
    const float* cb   = (const float*)d_in[6];
    const float* cr   = (const float*)d_in[7];
    const float* rw   = (const float*)d_in[8];
    const float* rb   = (const float*)d_in[9];
    const float* rr   = (const float*)d_in[10];
    const float* lg   = (const float*)d_in[11];
    const float* lb   = (const float*)d_in[12];
    const int* e_nn   = (const int*)d_in[13];
    const int* e_net  = (const int*)d_in[14];
    float* out = (float*)d_out;

    int E  = in_sizes[13] / 2;
    int NI = out_size / 512;

    float *p_h, *p_P, *p_A, *p_B, *p_H1;
    float *p_deg0, *p_deg1, *p_dis0, *p_dis1, *p_dinv0, *p_dinv1;
    cudaGetSymbolAddress((void**)&p_h, g_h);
    cudaGetSymbolAddress((void**)&p_P, g_P);
    cudaGetSymbolAddress((void**)&p_A, g_A);
    cudaGetSymbolAddress((void**)&p_B, g_B);
    cudaGetSymbolAddress((void**)&p_H1, g_H1);
    cudaGetSymbolAddress((void**)&p_deg0, g_deg0);
    cudaGetSymbolAddress((void**)&p_deg1, g_deg1);
    cudaGetSymbolAddress((void**)&p_dis0, g_dis0);
    cudaGetSymbolAddress((void**)&p_dis1, g_dis1);
    cudaGetSymbolAddress((void**)&p_dinv0, g_dinv0);
    cudaGetSymbolAddress((void**)&p_dinv1, g_dinv1);

    cudaFuncSetAttribute(k_mma, cudaFuncAttributeMaxDynamicSharedMemorySize, SM_BYTES);

    const int nblkN = (NN + 255) / 256;
    const int nblkE = (E + 255) / 256;
    const int gblk  = (NN + 127) / 128;

    k_initdeg<<<nblkN, 256>>>();
    k_count<<<nblkE, 256>>>(e_nn, p_deg0, E);
    k_count<<<nblkE, 256>>>(e_net, p_deg1, E);
    k_finishdeg<<<nblkN, 256>>>();

    k_enc1<<<NN / 8, 256>>>(x, ew1, eb1);
    k_mma<<<gblk, 256, SM_BYTES>>>(p_H1, ew2, eb2, nullptr, nullptr, nullptr,
                                   nullptr, p_h, out, 256, 0, NI);

    const int scblk = (E * 32 + 255) / 256;
    for (int l = 0; l < 3; l++) {
        k_mma<<<gblk, 256, SM_BYTES>>>(p_h, cw + l * 16384, cb + l * 128, cr + l * 128,
                                       p_dinv0, p_dis0, p_P, p_A, nullptr, 128, 1, NI);
        k_scatter<<<scblk, 256>>>(e_nn, p_dis0, p_P, p_A, E);
        k_mma<<<gblk, 256, SM_BYTES>>>(p_A, rw + l * 16384, rb + l * 128, rr + l * 128,
                                       p_dinv1, p_dis1, p_P, p_B, nullptr, 128, 1, NI);
        k_scatter<<<scblk, 256>>>(e_net, p_dis1, p_P, p_B, E);
        k_ln<<<NN / 8, 256>>>(p_B, lg + l * 128, lb + l * 128, p_h, out, l, NI);
    }
}

// round 6
// speedup vs baseline: 2.0299x; 1.1601x over previous
#include <cuda_runtime.h>
#include <cuda_fp16.h>
#include <cstdint>
#include <cstddef>

#define NN 200000
#define EMBD 128
#define LDK 72    // A tile row stride in halves (64 data + 8 pad)
#define LDB 136   // B tile row stride in halves (128 data + 8 pad)

// ---------------- scratch (device globals; no allocation) ----------------
__device__ float g_h [(size_t)NN * EMBD];
__device__ float g_P [(size_t)NN * EMBD];
__device__ float g_A [(size_t)NN * EMBD];
__device__ float g_B [(size_t)NN * EMBD];
__device__ float g_H1[(size_t)NN * 256];
__device__ float g_deg0[NN], g_deg1[NN];
__device__ float g_dis0[NN], g_dis1[NN];
__device__ float g_dinv0[NN], g_dinv1[NN];
// converted weights: [enc2: 256x128][conv0..2: 128x128][reconv0..2: 128x128]
#define WTOT (32768 + 6 * 16384)
__device__ __half g_Wh[WTOT];
__device__ __half g_Wl[WTOT];

__device__ __forceinline__ float leaky_f(float v) { return v >= 0.f ? v : 0.1f * v; }
__device__ __forceinline__ float relu_f(float v)  { return v > 0.f ? v : 0.f; }

__device__ __forceinline__ uint32_t smem_u32(const void* p) {
    uint32_t a;
    asm("{ .reg .u64 t; cvta.to.shared.u64 t, %1; cvt.u32.u64 %0, t; }" : "=r"(a) : "l"(p));
    return a;
}
__device__ __forceinline__ void ldsm_x4(uint32_t* r, uint32_t a) {
    asm volatile("ldmatrix.sync.aligned.m8n8.x4.shared.b16 {%0,%1,%2,%3}, [%4];"
                 : "=r"(r[0]), "=r"(r[1]), "=r"(r[2]), "=r"(r[3]) : "r"(a));
}
__device__ __forceinline__ void ldsm_x4t(uint32_t* r, uint32_t a) {
    asm volatile("ldmatrix.sync.aligned.m8n8.x4.trans.shared.b16 {%0,%1,%2,%3}, [%4];"
                 : "=r"(r[0]), "=r"(r[1]), "=r"(r[2]), "=r"(r[3]) : "r"(a));
}
__device__ __forceinline__ void mma_fp16(float* d, const uint32_t* a, const uint32_t* b) {
    asm volatile("mma.sync.aligned.m16n8k16.row.col.f32.f16.f16.f32 "
                 "{%0,%1,%2,%3}, {%4,%5,%6,%7}, {%8,%9}, {%0,%1,%2,%3};"
                 : "+f"(d[0]), "+f"(d[1]), "+f"(d[2]), "+f"(d[3])
                 : "r"(a[0]), "r"(a[1]), "r"(a[2]), "r"(a[3]), "r"(b[0]), "r"(b[1]));
}

// ---------------- degree kernels ----------------
__global__ void k_initdeg() {
    int i = blockIdx.x * 256 + threadIdx.x;
    if (i < NN) { g_deg0[i] = 1.f; g_deg1[i] = 1.f; }
}
__global__ void k_count(const int* __restrict__ edges, float* __restrict__ deg, int E) {
    int i = blockIdx.x * 256 + threadIdx.x;
    if (i < E) atomicAdd(&deg[edges[i]], 1.f);
}
__global__ void k_finishdeg() {
    int i = blockIdx.x * 256 + threadIdx.x;
    if (i < NN) {
        float d0 = g_deg0[i], d1 = g_deg1[i];
        g_dis0[i] = rsqrtf(d0); g_dinv0[i] = 1.0f / d0;
        g_dis1[i] = rsqrtf(d1); g_dinv1[i] = 1.0f / d1;
    }
}

// ---------------- weight pre-conversion (fp32 -> fp16 hi/lo), once per launch ----
__global__ void k_cvtW(const float* __restrict__ ew2, const float* __restrict__ cw,
                       const float* __restrict__ rw) {
    int idx = blockIdx.x * 256 + threadIdx.x;
    if (idx >= WTOT) return;
    float v;
    if (idx < 32768) v = ew2[idx];
    else {
        int i2 = idx - 32768;
        int m = i2 >> 14, r = i2 & 16383;
        v = (m < 3) ? cw[m * 16384 + r] : rw[(m - 3) * 16384 + r];
    }
    __half h = __float2half_rn(v);
    g_Wh[idx] = h;
    g_Wl[idx] = __float2half_rn(v - __half2float(h));
}

// ---------------- encoder layer 1 ----------------
__global__ void k_enc1(const float* __restrict__ x, const float* __restrict__ W1,
                       const float* __restrict__ b1) {
    __shared__ float sW[32 * 256];
    int t = threadIdx.x;
    {
        float4* sv = (float4*)sW;
        const float4* wv = (const float4*)W1;
        #pragma unroll
        for (int i = 0; i < 8; i++) sv[t + 256 * i] = wv[t + 256 * i];
    }
    __syncthreads();
    int wid = t >> 5, lane = t & 31;
    int node = blockIdx.x * 8 + wid;
    float xv = x[(size_t)node * 32 + lane];
    float acc[8];
    #pragma unroll
    for (int i = 0; i < 8; i++) acc[i] = b1[lane + 32 * i];
    #pragma unroll
    for (int k = 0; k < 32; k++) {
        float xk = __shfl_sync(0xffffffffu, xv, k);
        #pragma unroll
        for (int i = 0; i < 8; i++) acc[i] += xk * sW[k * 256 + lane + 32 * i];
    }
    float* dst = g_H1 + (size_t)node * 256;
    #pragma unroll
    for (int i = 0; i < 8; i++) dst[lane + 32 * i] = leaky_f(acc[i]);
}

// ---------------- HMMA GEMM: C[128x128] = A[M,K] @ W[K,128], fp16 3-pass split ----
// K chunked by 64. smem: Ah,Al [128x72], Bh,Bl [64x136] halves => 71,680 B -> 2 CTA/SM
#define OFF_AL 9216
#define OFF_BH 18432
#define OFF_BL 27136
#define SM_BYTES (35840 * 2)

__global__ void __launch_bounds__(256, 2)
k_mma(const float* __restrict__ A, const __half* __restrict__ Wh,
      const __half* __restrict__ Wl,
      const float* __restrict__ bias, const float* __restrict__ root,
      const float* __restrict__ dinv, const float* __restrict__ dis,
      float* __restrict__ P, float* __restrict__ AGG, float* __restrict__ out,
      int K, int mode, int NI) {
    extern __shared__ __half smem[];
    __half* sAh = smem;
    __half* sAl = smem + OFF_AL;
    __half* sBh = smem + OFF_BH;
    __half* sBl = smem + OFF_BL;

    int tid = threadIdx.x, lane = tid & 31, w = tid >> 5;
    int wm = w & 3, wn = w >> 2;
    int r0 = blockIdx.x * 128;

    float acc[2][8][4];
    #pragma unroll
    for (int i = 0; i < 2; i++)
        #pragma unroll
        for (int n = 0; n < 8; n++)
            #pragma unroll
            for (int q = 0; q < 4; q++) acc[i][n][q] = 0.f;

    uint32_t sb = smem_u32(smem);
    uint32_t aAh = sb + 2 * ((wm * 32 + (lane & 15)) * LDK + (lane >> 4) * 8);
    uint32_t aAl = aAh + OFF_AL * 2;
    uint32_t aBh = sb + OFF_BH * 2 + 2 * ((lane & 15) * LDB + wn * 64 + (lane >> 4) * 8);
    uint32_t aBl = aBh + (OFF_BL - OFF_BH) * 2;

    for (int kc = 0; kc < K; kc += 64) {
        if (kc) __syncthreads();
        // ---- stage A chunk (128 rows x 64 k) as fp16 hi/lo ----
        #pragma unroll
        for (int i = 0; i < 8; i++) {
            int idx = tid + 256 * i;
            int r = idx >> 4, kg = (idx & 15) * 4;
            int rr = r0 + r; if (rr >= NN) rr = NN - 1;
            float4 a = *(const float4*)(A + (size_t)rr * K + kc + kg);
            __half2 h01 = __floats2half2_rn(a.x, a.y);
            __half2 h23 = __floats2half2_rn(a.z, a.w);
            float2 f01 = __half22float2(h01);
            float2 f23 = __half22float2(h23);
            __half2 l01 = __floats2half2_rn(a.x - f01.x, a.y - f01.y);
            __half2 l23 = __floats2half2_rn(a.z - f23.x, a.w - f23.y);
            int off = r * LDK + kg;
            uint2 vh; vh.x = *(uint32_t*)&h01; vh.y = *(uint32_t*)&h23;
            uint2 vl; vl.x = *(uint32_t*)&l01; vl.y = *(uint32_t*)&l23;
            *(uint2*)(sAh + off) = vh;
            *(uint2*)(sAl + off) = vl;
        }
        // ---- stage W chunk (64 k-rows x 128 n), already fp16 ----
        #pragma unroll
        for (int i = 0; i < 8; i++) {
            int idx = tid + 256 * i;
            int kk = idx >> 5, ng = (idx & 31) * 4;
            int off = kk * LDB + ng;
            size_t goff = (size_t)(kc + kk) * 128 + ng;
            *(uint2*)(sBh + off) = *(const uint2*)(Wh + goff);
            *(uint2*)(sBl + off) = *(const uint2*)(Wl + goff);
        }
        __syncthreads();

        // ---- mainloop: 4 k-steps of k16 ----
        #pragma unroll
        for (int ks = 0; ks < 4; ks++) {
            uint32_t ah[2][4], al[2][4];
            #pragma unroll
            for (int i = 0; i < 2; i++) {
                ldsm_x4(ah[i], aAh + i * (16 * LDK * 2) + ks * 32);
                ldsm_x4(al[i], aAl + i * (16 * LDK * 2) + ks * 32);
            }
            #pragma unroll
            for (int j = 0; j < 4; j++) {
                uint32_t bh[4], bl[4];
                ldsm_x4t(bh, aBh + ks * (16 * LDB * 2) + j * 32);
                ldsm_x4t(bl, aBl + ks * (16 * LDB * 2) + j * 32);
                #pragma unroll
                for (int i = 0; i < 2; i++) {
                    mma_fp16(acc[i][2 * j],     ah[i], &bh[0]);
                    mma_fp16(acc[i][2 * j + 1], ah[i], &bh[2]);
                    mma_fp16(acc[i][2 * j],     al[i], &bh[0]);
                    mma_fp16(acc[i][2 * j + 1], al[i], &bh[2]);
                    mma_fp16(acc[i][2 * j],     ah[i], &bl[0]);
                    mma_fp16(acc[i][2 * j + 1], ah[i], &bl[2]);
                }
            }
        }
    }

    // ---- epilogue ----
    int rbase = r0 + wm * 32;
    int cb = wn * 64 + (lane & 3) * 2;
    #pragma unroll
    for (int i = 0; i < 2; i++) {
        #pragma unroll
        for (int q2 = 0; q2 < 2; q2++) {
            int r = rbase + i * 16 + (lane >> 2) + q2 * 8;
            if (r >= NN) continue;
            if (mode == 0) {
                #pragma unroll
                for (int n = 0; n < 8; n++) {
                    int c = cb + n * 8;
                    float2 o;
                    o.x = leaky_f(acc[i][n][q2 * 2]     + bias[c]);
                    o.y = leaky_f(acc[i][n][q2 * 2 + 1] + bias[c + 1]);
                    *(float2*)(AGG + (size_t)r * 128 + c) = o;
                    if (r < NI) *(float2*)(out + (size_t)r * 512 + c) = o;
                }
            } else {
                float di = dinv[r], ds = dis[r];
                #pragma unroll
                for (int n = 0; n < 8; n++) {
                    int c = cb + n * 8;
                    float v0 = acc[i][n][q2 * 2]     + bias[c];
                    float v1 = acc[i][n][q2 * 2 + 1] + bias[c + 1];
                    float2 p, s;
                    p.x = ds * relu_f(v0); p.y = ds * relu_f(v1);
                    s.x = relu_f(v0 + root[c]) * di;
                    s.y = relu_f(v1 + root[c + 1]) * di;
                    *(float2*)(P   + (size_t)r * 128 + c) = p;
                    *(float2*)(AGG + (size_t)r * 128 + c) = s;
                }
            }
        }
    }
}

// ---------------- scatter: AGG[col] += dis[col] * P[row], warp per edge ----------------
__global__ void k_scatter(const int* __restrict__ edges, const float* __restrict__ dis,
                          const float* __restrict__ P, float* __restrict__ AGG, int E) {
    int w = (blockIdx.x * blockDim.x + threadIdx.x) >> 5;
    if (w >= E) return;
    int lane = threadIdx.x & 31;
    int row = __ldg(&edges[w]);
    int col = __ldg(&edges[E + w]);
    float nrm = __ldg(&dis[col]);
    const float4* src = (const float4*)(P + (size_t)row * 128);
    float4* dst = (float4*)(AGG + (size_t)col * 128);
    float4 v = __ldg(&src[lane]);
    asm volatile("red.global.add.v4.f32 [%0], {%1, %2, %3, %4};"
                 :: "l"(dst + lane), "f"(nrm * v.x), "f"(nrm * v.y),
                    "f"(nrm * v.z), "f"(nrm * v.w)
                 : "memory");
}

// ---------------- layernorm + leaky + residual ----------------
__global__ void k_ln(const float* __restrict__ Bin, const float* __restrict__ gamma,
                     const float* __restrict__ beta, float* __restrict__ h,
                     float* __restrict__ out, int l, int NI) {
    int t = threadIdx.x;
    int lane = t & 31;
    int node = blockIdx.x * 8 + (t >> 5);
    float4 v = ((const float4*)(Bin + (size_t)node * 128))[lane];
    float s = v.x + v.y + v.z + v.w;
    #pragma unroll
    for (int o = 16; o > 0; o >>= 1) s += __shfl_xor_sync(0xffffffffu, s, o);
    float mu = s * (1.0f / 128.0f);
    float dx = v.x - mu, dy = v.y - mu, dz = v.z - mu, dw = v.w - mu;
    float q = dx * dx + dy * dy + dz * dz + dw * dw;
    #pragma unroll
    for (int o = 16; o > 0; o >>= 1) q += __shfl_xor_sync(0xffffffffu, q, o);
    float rs = rsqrtf(q * (1.0f / 128.0f) + 1e-5f);
    float4 gg = ((const float4*)gamma)[lane];
    float4 bb = ((const float4*)beta)[lane];
    float4 hp = ((const float4*)(h + (size_t)node * 128))[lane];
    float4 o4;
    o4.x = leaky_f(dx * rs * gg.x + bb.x) + hp.x;
    o4.y = leaky_f(dy * rs * gg.y + bb.y) + hp.y;
    o4.z = leaky_f(dz * rs * gg.z + bb.z) + hp.z;
    o4.w = leaky_f(dw * rs * gg.w + bb.w) + hp.w;
    ((float4*)(h + (size_t)node * 128))[lane] = o4;
    if (node < NI) ((float4*)(out + (size_t)node * 512 + (l + 1) * 128))[lane] = o4;
}

// ---------------- host ----------------
extern "C" void kernel_launch(void* const* d_in, const int* in_sizes, int n_in,
                              void* d_out, int out_size) {
    const float* x    = (const float*)d_in[0];
    const float* ew1  = (const float*)d_in[1];
    const float* eb1  = (const float*)d_in[2];
    const float* ew2  = (const float*)d_in[3];
    const float* eb2  = (const float*)d_in[4];
    const float* cw   = (const float*)d_in[5];
    const float* cb   = (const float*)d_in[6];
    const float* cr   = (const float*)d_in[7];
    const float* rw   = (const float*)d_in[8];
    const float* rb   = (const float*)d_in[9];
    const float* rr   = (const float*)d_in[10];
    const float* lg   = (const float*)d_in[11];
    const float* lb   = (const float*)d_in[12];
    const int* e_nn   = (const int*)d_in[13];
    const int* e_net  = (const int*)d_in[14];
    float* out = (float*)d_out;

    int E  = in_sizes[13] / 2;
    int NI = out_size / 512;

    float *p_h, *p_P, *p_A, *p_B, *p_H1;
    float *p_deg0, *p_deg1, *p_dis0, *p_dis1, *p_dinv0, *p_dinv1;
    __half *p_Wh, *p_Wl;
    cudaGetSymbolAddress((void**)&p_h, g_h);
    cudaGetSymbolAddress((void**)&p_P, g_P);
    cudaGetSymbolAddress((void**)&p_A, g_A);
    cudaGetSymbolAddress((void**)&p_B, g_B);
    cudaGetSymbolAddress((void**)&p_H1, g_H1);
    cudaGetSymbolAddress((void**)&p_deg0, g_deg0);
    cudaGetSymbolAddress((void**)&p_deg1, g_deg1);
    cudaGetSymbolAddress((void**)&p_dis0, g_dis0);
    cudaGetSymbolAddress((void**)&p_dis1, g_dis1);
    cudaGetSymbolAddress((void**)&p_dinv0, g_dinv0);
    cudaGetSymbolAddress((void**)&p_dinv1, g_dinv1);
    cudaGetSymbolAddress((void**)&p_Wh, g_Wh);
    cudaGetSymbolAddress((void**)&p_Wl, g_Wl);

    cudaFuncSetAttribute(k_mma, cudaFuncAttributeMaxDynamicSharedMemorySize, SM_BYTES);

    const int nblkN = (NN + 255) / 256;
    const int nblkE = (E + 255) / 256;
    const int gblk  = (NN + 127) / 128;

    k_initdeg<<<nblkN, 256>>>();
    k_count<<<nblkE, 256>>>(e_nn, p_deg0, E);
    k_count<<<nblkE, 256>>>(e_net, p_deg1, E);
    k_finishdeg<<<nblkN, 256>>>();
    k_cvtW<<<(WTOT + 255) / 256, 256>>>(ew2, cw, rw);

    k_enc1<<<NN / 8, 256>>>(x, ew1, eb1);
    k_mma<<<gblk, 256, SM_BYTES>>>(p_H1, p_Wh, p_Wl, eb2, nullptr, nullptr, nullptr,
                                   nullptr, p_h, out, 256, 0, NI);

    const int scblk = (E * 32 + 255) / 256;
    for (int l = 0; l < 3; l++) {
        k_mma<<<gblk, 256, SM_BYTES>>>(p_h, p_Wh + 32768 + l * 16384,
                                       p_Wl + 32768 + l * 16384,
                                       cb + l * 128, cr + l * 128,
                                       p_dinv0, p_dis0, p_P, p_A, nullptr, 128, 1, NI);
        k_scatter<<<scblk, 256>>>(e_nn, p_dis0, p_P, p_A, E);
        k_mma<<<gblk, 256, SM_BYTES>>>(p_A, p_Wh + 81920 + l * 16384,
                                       p_Wl + 81920 + l * 16384,
                                       rb + l * 128, rr + l * 128,
                                       p_dinv1, p_dis1, p_P, p_B, nullptr, 128, 1, NI);
        k_scatter<<<scblk, 256>>>(e_net, p_dis1, p_P, p_B, E);
        k_ln<<<NN / 8, 256>>>(p_B, lg + l * 128, lb + l * 128, p_h, out, l, NI);
    }
}

// round 9
// speedup vs baseline: 2.1345x; 1.0515x over previous
#include <cuda_runtime.h>
#include <cuda_fp16.h>
#include <cstdint>
#include <cstddef>

#define NN 200000
#define EMBD 128
#define LDK 72    // A tile row stride in halves (64 data + 8 pad)
#define LDB 136   // B tile row stride in halves (128 data + 8 pad)

// ---------------- scratch (device globals; no allocation) ----------------
__device__ float g_h [(size_t)NN * EMBD];
__device__ __half g_P [(size_t)NN * EMBD];   // fp16 messages
__device__ float g_A [(size_t)NN * EMBD];
__device__ float g_B [(size_t)NN * EMBD];
__device__ float g_H1[(size_t)NN * 256];
__device__ float g_deg0[NN], g_deg1[NN];
__device__ float g_dis0[NN], g_dis1[NN];
__device__ float g_dinv0[NN], g_dinv1[NN];
// converted weights: [enc2: 256x128][conv0..2: 128x128][reconv0..2: 128x128]
#define WTOT (32768 + 6 * 16384)
__device__ __half g_Wh[WTOT];
__device__ __half g_Wl[WTOT];

__device__ __forceinline__ float leaky_f(float v) { return v >= 0.f ? v : 0.1f * v; }
__device__ __forceinline__ float relu_f(float v)  { return v > 0.f ? v : 0.f; }

__device__ __forceinline__ uint32_t smem_u32(const void* p) {
    uint32_t a;
    asm("{ .reg .u64 t; cvta.to.shared.u64 t, %1; cvt.u32.u64 %0, t; }" : "=r"(a) : "l"(p));
    return a;
}
__device__ __forceinline__ void ldsm_x4(uint32_t* r, uint32_t a) {
    asm volatile("ldmatrix.sync.aligned.m8n8.x4.shared.b16 {%0,%1,%2,%3}, [%4];"
                 : "=r"(r[0]), "=r"(r[1]), "=r"(r[2]), "=r"(r[3]) : "r"(a));
}
__device__ __forceinline__ void ldsm_x4t(uint32_t* r, uint32_t a) {
    asm volatile("ldmatrix.sync.aligned.m8n8.x4.trans.shared.b16 {%0,%1,%2,%3}, [%4];"
                 : "=r"(r[0]), "=r"(r[1]), "=r"(r[2]), "=r"(r[3]) : "r"(a));
}
__device__ __forceinline__ void mma_fp16(float* d, const uint32_t* a, const uint32_t* b) {
    asm volatile("mma.sync.aligned.m16n8k16.row.col.f32.f16.f16.f32 "
                 "{%0,%1,%2,%3}, {%4,%5,%6,%7}, {%8,%9}, {%0,%1,%2,%3};"
                 : "+f"(d[0]), "+f"(d[1]), "+f"(d[2]), "+f"(d[3])
                 : "r"(a[0]), "r"(a[1]), "r"(a[2]), "r"(a[3]), "r"(b[0]), "r"(b[1]));
}

// ---------------- degree kernels ----------------
__global__ void k_initdeg() {
    int i = blockIdx.x * 256 + threadIdx.x;
    if (i < NN) { g_deg0[i] = 1.f; g_deg1[i] = 1.f; }
}
__global__ void k_count(const int* __restrict__ edges, float* __restrict__ deg, int E) {
    int i = blockIdx.x * 256 + threadIdx.x;
    if (i < E) atomicAdd(&deg[edges[i]], 1.f);
}
__global__ void k_finishdeg() {
    int i = blockIdx.x * 256 + threadIdx.x;
    if (i < NN) {
        float d0 = g_deg0[i], d1 = g_deg1[i];
        g_dis0[i] = rsqrtf(d0); g_dinv0[i] = 1.0f / d0;
        g_dis1[i] = rsqrtf(d1); g_dinv1[i] = 1.0f / d1;
    }
}

// ---------------- weight pre-conversion (fp32 -> fp16 hi/lo), once per launch ----
__global__ void k_cvtW(const float* __restrict__ ew2, const float* __restrict__ cw,
                       const float* __restrict__ rw) {
    int idx = blockIdx.x * 256 + threadIdx.x;
    if (idx >= WTOT) return;
    float v;
    if (idx < 32768) v = ew2[idx];
    else {
        int i2 = idx - 32768;
        int m = i2 >> 14, r = i2 & 16383;
        v = (m < 3) ? cw[m * 16384 + r] : rw[(m - 3) * 16384 + r];
    }
    __half h = __float2half_rn(v);
    g_Wh[idx] = h;
    g_Wl[idx] = __float2half_rn(v - __half2float(h));
}

// ---------------- encoder layer 1 ----------------
__global__ void k_enc1(const float* __restrict__ x, const float* __restrict__ W1,
                       const float* __restrict__ b1) {
    __shared__ float sW[32 * 256];
    int t = threadIdx.x;
    {
        float4* sv = (float4*)sW;
        const float4* wv = (const float4*)W1;
        #pragma unroll
        for (int i = 0; i < 8; i++) sv[t + 256 * i] = wv[t + 256 * i];
    }
    __syncthreads();
    int wid = t >> 5, lane = t & 31;
    int node = blockIdx.x * 8 + wid;
    float xv = x[(size_t)node * 32 + lane];
    float acc[8];
    #pragma unroll
    for (int i = 0; i < 8; i++) acc[i] = b1[lane + 32 * i];
    #pragma unroll
    for (int k = 0; k < 32; k++) {
        float xk = __shfl_sync(0xffffffffu, xv, k);
        #pragma unroll
        for (int i = 0; i < 8; i++) acc[i] += xk * sW[k * 256 + lane + 32 * i];
    }
    float* dst = g_H1 + (size_t)node * 256;
    #pragma unroll
    for (int i = 0; i < 8; i++) dst[lane + 32 * i] = leaky_f(acc[i]);
}

// ---------------- HMMA GEMM: C[128x128] = A[M,K] @ W[K,128], fp16 3-pass split ----
// K chunked by 64. smem: Ah,Al [128x72], Bh,Bl [64x136] halves => 71,680 B -> 2 CTA/SM
#define OFF_AL 9216
#define OFF_BH 18432
#define OFF_BL 27136
#define SM_BYTES (35840 * 2)

__global__ void __launch_bounds__(256, 2)
k_mma(const float* __restrict__ A, const __half* __restrict__ Wh,
      const __half* __restrict__ Wl,
      const float* __restrict__ bias, const float* __restrict__ root,
      const float* __restrict__ dinv, const float* __restrict__ dis,
      __half* __restrict__ P, float* __restrict__ AGG, float* __restrict__ out,
      int K, int mode, int NI) {
    extern __shared__ __half smem[];
    __half* sAh = smem;
    __half* sAl = smem + OFF_AL;
    __half* sBh = smem + OFF_BH;
    __half* sBl = smem + OFF_BL;

    int tid = threadIdx.x, lane = tid & 31, w = tid >> 5;
    int wm = w & 3, wn = w >> 2;
    int r0 = blockIdx.x * 128;

    float acc[2][8][4];
    #pragma unroll
    for (int i = 0; i < 2; i++)
        #pragma unroll
        for (int n = 0; n < 8; n++)
            #pragma unroll
            for (int q = 0; q < 4; q++) acc[i][n][q] = 0.f;

    uint32_t sb = smem_u32(smem);
    uint32_t aAh = sb + 2 * ((wm * 32 + (lane & 15)) * LDK + (lane >> 4) * 8);
    uint32_t aAl = aAh + OFF_AL * 2;
    uint32_t aBh = sb + OFF_BH * 2 + 2 * ((lane & 15) * LDB + wn * 64 + (lane >> 4) * 8);
    uint32_t aBl = aBh + (OFF_BL - OFF_BH) * 2;

    for (int kc = 0; kc < K; kc += 64) {
        if (kc) __syncthreads();
        // ---- stage A chunk (128 rows x 64 k) as fp16 hi/lo ----
        #pragma unroll
        for (int i = 0; i < 8; i++) {
            int idx = tid + 256 * i;
            int r = idx >> 4, kg = (idx & 15) * 4;
            int rr = r0 + r; if (rr >= NN) rr = NN - 1;
            float4 a = *(const float4*)(A + (size_t)rr * K + kc + kg);
            __half2 h01 = __floats2half2_rn(a.x, a.y);
            __half2 h23 = __floats2half2_rn(a.z, a.w);
            float2 f01 = __half22float2(h01);
            float2 f23 = __half22float2(h23);
            __half2 l01 = __floats2half2_rn(a.x - f01.x, a.y - f01.y);
            __half2 l23 = __floats2half2_rn(a.z - f23.x, a.w - f23.y);
            int off = r * LDK + kg;
            uint2 vh; vh.x = *(uint32_t*)&h01; vh.y = *(uint32_t*)&h23;
            uint2 vl; vl.x = *(uint32_t*)&l01; vl.y = *(uint32_t*)&l23;
            *(uint2*)(sAh + off) = vh;
            *(uint2*)(sAl + off) = vl;
        }
        // ---- stage W chunk (64 k-rows x 128 n), already fp16 ----
        #pragma unroll
        for (int i = 0; i < 8; i++) {
            int idx = tid + 256 * i;
            int kk = idx >> 5, ng = (idx & 31) * 4;
            int off = kk * LDB + ng;
            size_t goff = (size_t)(kc + kk) * 128 + ng;
            *(uint2*)(sBh + off) = *(const uint2*)(Wh + goff);
            *(uint2*)(sBl + off) = *(const uint2*)(Wl + goff);
        }
        __syncthreads();

        // ---- mainloop: 4 k-steps of k16 ----
        #pragma unroll
        for (int ks = 0; ks < 4; ks++) {
            uint32_t ah[2][4], al[2][4];
            #pragma unroll
            for (int i = 0; i < 2; i++) {
                ldsm_x4(ah[i], aAh + i * (16 * LDK * 2) + ks * 32);
                ldsm_x4(al[i], aAl + i * (16 * LDK * 2) + ks * 32);
            }
            #pragma unroll
            for (int j = 0; j < 4; j++) {
                uint32_t bh[4], bl[4];
                ldsm_x4t(bh, aBh + ks * (16 * LDB * 2) + j * 32);
                ldsm_x4t(bl, aBl + ks * (16 * LDB * 2) + j * 32);
                #pragma unroll
                for (int i = 0; i < 2; i++) {
                    mma_fp16(acc[i][2 * j],     ah[i], &bh[0]);
                    mma_fp16(acc[i][2 * j + 1], ah[i], &bh[2]);
                    mma_fp16(acc[i][2 * j],     al[i], &bh[0]);
                    mma_fp16(acc[i][2 * j + 1], al[i], &bh[2]);
                    mma_fp16(acc[i][2 * j],     ah[i], &bl[0]);
                    mma_fp16(acc[i][2 * j + 1], ah[i], &bl[2]);
                }
            }
        }
    }

    // ---- epilogue ----
    int rbase = r0 + wm * 32;
    int cb = wn * 64 + (lane & 3) * 2;
    #pragma unroll
    for (int i = 0; i < 2; i++) {
        #pragma unroll
        for (int q2 = 0; q2 < 2; q2++) {
            int r = rbase + i * 16 + (lane >> 2) + q2 * 8;
            if (r >= NN) continue;
            if (mode == 0) {
                #pragma unroll
                for (int n = 0; n < 8; n++) {
                    int c = cb + n * 8;
                    float2 o;
                    o.x = leaky_f(acc[i][n][q2 * 2]     + bias[c]);
                    o.y = leaky_f(acc[i][n][q2 * 2 + 1] + bias[c + 1]);
                    *(float2*)(AGG + (size_t)r * 128 + c) = o;
                    if (r < NI) *(float2*)(out + (size_t)r * 512 + c) = o;
                }
            } else {
                float di = dinv[r], ds = dis[r];
                #pragma unroll
                for (int n = 0; n < 8; n++) {
                    int c = cb + n * 8;
                    float v0 = acc[i][n][q2 * 2]     + bias[c];
                    float v1 = acc[i][n][q2 * 2 + 1] + bias[c + 1];
                    *(__half2*)(P + (size_t)r * 128 + c) =
                        __floats2half2_rn(ds * relu_f(v0), ds * relu_f(v1));
                    float2 s;
                    s.x = relu_f(v0 + root[c]) * di;
                    s.y = relu_f(v1 + root[c + 1]) * di;
                    *(float2*)(AGG + (size_t)r * 128 + c) = s;
                }
            }
        }
    }
}

// ---------------- scatter: AGG[col] += dis[col] * P[row], warp per edge ----------------
__global__ void k_scatter(const int* __restrict__ edges, const float* __restrict__ dis,
                          const __half* __restrict__ P, float* __restrict__ AGG, int E) {
    int w = (blockIdx.x * blockDim.x + threadIdx.x) >> 5;
    if (w >= E) return;
    int lane = threadIdx.x & 31;
    int row = __ldg(&edges[w]);
    int col = __ldg(&edges[E + w]);
    float nrm = __ldg(&dis[col]);
    const uint2* src = (const uint2*)(P + (size_t)row * 128);
    float4* dst = (float4*)(AGG + (size_t)col * 128);
    uint2 pv = __ldg(&src[lane]);
    __half2 p01 = *(__half2*)&pv.x;
    __half2 p23 = *(__half2*)&pv.y;
    float2 f01 = __half22float2(p01);
    float2 f23 = __half22float2(p23);
    asm volatile("red.global.add.v4.f32 [%0], {%1, %2, %3, %4};"
                 :: "l"(dst + lane), "f"(nrm * f01.x), "f"(nrm * f01.y),
                    "f"(nrm * f23.x), "f"(nrm * f23.y)
                 : "memory");
}

// ---------------- layernorm + leaky + residual ----------------
__global__ void k_ln(const float* __restrict__ Bin, const float* __restrict__ gamma,
                     const float* __restrict__ beta, float* __restrict__ h,
                     float* __restrict__ out, int l, int NI) {
    int t = threadIdx.x;
    int lane = t & 31;
    int node = blockIdx.x * 8 + (t >> 5);
    float4 v = ((const float4*)(Bin + (size_t)node * 128))[lane];
    float s = v.x + v.y + v.z + v.w;
    #pragma unroll
    for (int o = 16; o > 0; o >>= 1) s += __shfl_xor_sync(0xffffffffu, s, o);
    float mu = s * (1.0f / 128.0f);
    float dx = v.x - mu, dy = v.y - mu, dz = v.z - mu, dw = v.w - mu;
    float q = dx * dx + dy * dy + dz * dz + dw * dw;
    #pragma unroll
    for (int o = 16; o > 0; o >>= 1) q += __shfl_xor_sync(0xffffffffu, q, o);
    float rs = rsqrtf(q * (1.0f / 128.0f) + 1e-5f);
    float4 gg = ((const float4*)gamma)[lane];
    float4 bb = ((const float4*)beta)[lane];
    float4 hp = ((const float4*)(h + (size_t)node * 128))[lane];
    float4 o4;
    o4.x = leaky_f(dx * rs * gg.x + bb.x) + hp.x;
    o4.y = leaky_f(dy * rs * gg.y + bb.y) + hp.y;
    o4.z = leaky_f(dz * rs * gg.z + bb.z) + hp.z;
    o4.w = leaky_f(dw * rs * gg.w + bb.w) + hp.w;
    ((float4*)(h + (size_t)node * 128))[lane] = o4;
    if (node < NI) ((float4*)(out + (size_t)node * 512 + (l + 1) * 128))[lane] = o4;
}

// ---------------- host ----------------
extern "C" void kernel_launch(void* const* d_in, const int* in_sizes, int n_in,
                              void* d_out, int out_size) {
    const float* x    = (const float*)d_in[0];
    const float* ew1  = (const float*)d_in[1];
    const float* eb1  = (const float*)d_in[2];
    const float* ew2  = (const float*)d_in[3];
    const float* eb2  = (const float*)d_in[4];
    const float* cw   = (const float*)d_in[5];
    const float* cb   = (const float*)d_in[6];
    const float* cr   = (const float*)d_in[7];
    const float* rw   = (const float*)d_in[8];
    const float* rb   = (const float*)d_in[9];
    const float* rr   = (const float*)d_in[10];
    const float* lg   = (const float*)d_in[11];
    const float* lb   = (const float*)d_in[12];
    const int* e_nn   = (const int*)d_in[13];
    const int* e_net  = (const int*)d_in[14];
    float* out = (float*)d_out;

    int E  = in_sizes[13] / 2;
    int NI = out_size / 512;

    float *p_h, *p_A, *p_B, *p_H1;
    __half *p_P;
    float *p_deg0, *p_deg1, *p_dis0, *p_dis1, *p_dinv0, *p_dinv1;
    __half *p_Wh, *p_Wl;
    cudaGetSymbolAddress((void**)&p_h, g_h);
    cudaGetSymbolAddress((void**)&p_P, g_P);
    cudaGetSymbolAddress((void**)&p_A, g_A);
    cudaGetSymbolAddress((void**)&p_B, g_B);
    cudaGetSymbolAddress((void**)&p_H1, g_H1);
    cudaGetSymbolAddress((void**)&p_deg0, g_deg0);
    cudaGetSymbolAddress((void**)&p_deg1, g_deg1);
    cudaGetSymbolAddress((void**)&p_dis0, g_dis0);
    cudaGetSymbolAddress((void**)&p_dis1, g_dis1);
    cudaGetSymbolAddress((void**)&p_dinv0, g_dinv0);
    cudaGetSymbolAddress((void**)&p_dinv1, g_dinv1);
    cudaGetSymbolAddress((void**)&p_Wh, g_Wh);
    cudaGetSymbolAddress((void**)&p_Wl, g_Wl);

    cudaFuncSetAttribute(k_mma, cudaFuncAttributeMaxDynamicSharedMemorySize, SM_BYTES);

    const int nblkN = (NN + 255) / 256;
    const int nblkE = (E + 255) / 256;
    const int gblk  = (NN + 127) / 128;

    k_initdeg<<<nblkN, 256>>>();
    k_count<<<nblkE, 256>>>(e_nn, p_deg0, E);
    k_count<<<nblkE, 256>>>(e_net, p_deg1, E);
    k_finishdeg<<<nblkN, 256>>>();
    k_cvtW<<<(WTOT + 255) / 256, 256>>>(ew2, cw, rw);

    k_enc1<<<NN / 8, 256>>>(x, ew1, eb1);
    k_mma<<<gblk, 256, SM_BYTES>>>(p_H1, p_Wh, p_Wl, eb2, nullptr, nullptr, nullptr,
                                   nullptr, p_h, out, 256, 0, NI);

    const int scblk = (E * 32 + 255) / 256;
    for (int l = 0; l < 3; l++) {
        k_mma<<<gblk, 256, SM_BYTES>>>(p_h, p_Wh + 32768 + l * 16384,
                                       p_Wl + 32768 + l * 16384,
                                       cb + l * 128, cr + l * 128,
                                       p_dinv0, p_dis0, p_P, p_A, nullptr, 128, 1, NI);
        k_scatter<<<scblk, 256>>>(e_nn, p_dis0, p_P, p_A, E);
        k_mma<<<gblk, 256, SM_BYTES>>>(p_A, p_Wh + 81920 + l * 16384,
                                       p_Wl + 81920 + l * 16384,
                                       rb + l * 128, rr + l * 128,
                                       p_dinv1, p_dis1, p_P, p_B, nullptr, 128, 1, NI);
        k_scatter<<<scblk, 256>>>(e_net, p_dis1, p_P, p_B, E);
        k_ln<<<NN / 8, 256>>>(p_B, lg + l * 128, lb + l * 128, p_h, out, l, NI);
    }
}